// round 6
// baseline (speedup 1.0000x reference)
#include <cuda_runtime.h>

// ---------------------------------------------------------------------------
// LaplacianRegularization
//   degree = segment_sum(w, row)                       (N)
//   invd   = rsqrt(degree)                             (N)
//   diff_e = y[row]*invd[row] - y[col]*invd[col]       (E,16)
//   out    = mean_e( ||diff_e||_2 * w_e )              scalar
//
// Inputs (metadata order):
//   d_in[0] : edge_index  int64 OR int32 (2, E) -> row = ei[0:E], col = ei[E:2E]
//             (JAX with x64 disabled silently demotes int64 -> int32; we
//              detect the element width on-device, see k_detect)
//   d_in[1] : edge_weights float32 (E,)
//   d_in[2] : y            float32 (N, 16)
// Output: 1 float
// ---------------------------------------------------------------------------

#define MAX_NODES 131072

__device__ float    g_deg[MAX_NODES];
__device__ float    g_invd[MAX_NODES];
__device__ double   g_sum;
__device__ unsigned g_flag;   // !=0  =>  edge_index is int32

// --- index load helper: dispatch on detected dtype ---------------------------
__device__ __forceinline__ int load_idx(const void* ei, long long pos, bool is32) {
    if (is32) return ((const int*)ei)[pos];
    return (int)((const long long*)ei)[pos];
}

// --- K1: zero scratch (deterministic per call) -------------------------------
__global__ void k_zero(int n) {
    int i = blockIdx.x * blockDim.x + threadIdx.x;
    if (i < n) g_deg[i] = 0.0f;
    if (i == 0) { g_sum = 0.0; g_flag = 0u; }
}

// --- K1b: dtype probe ---------------------------------------------------------
// View buffer as 32-bit words. For int64 indices < 2^31 every odd word is the
// zero hi-half. For int32 the odd words are node indices (nonzero w.h.p. over
// 4096 random samples from U[0,100000)). OR them together.
__global__ void k_detect(const unsigned* __restrict__ words, int E) {
    int samples = E < 4096 ? E : 4096;
    unsigned v = 0;
    for (int i = threadIdx.x; i < samples; i += blockDim.x)
        v |= words[2 * i + 1];
    // warp + block OR-reduce
    #pragma unroll
    for (int o = 16; o > 0; o >>= 1)
        v |= __shfl_xor_sync(0xFFFFFFFFu, v, o);
    __shared__ unsigned s[8];
    int lane = threadIdx.x & 31, warp = threadIdx.x >> 5;
    if (lane == 0) s[warp] = v;
    __syncthreads();
    if (threadIdx.x == 0) {
        unsigned r = 0;
        for (int i = 0; i < (int)(blockDim.x >> 5); i++) r |= s[i];
        g_flag = r;
    }
}

// --- K2: degree = segment_sum(w, row) -----------------------------------------
__global__ void k_degree(const void* __restrict__ ei,
                         const float* __restrict__ w, int E, int N) {
    int e = blockIdx.x * blockDim.x + threadIdx.x;
    if (e >= E) return;
    const bool is32 = (g_flag != 0u);
    int r = load_idx(ei, e, is32);
    if ((unsigned)r < (unsigned)N)            // defensive: never trap
        atomicAdd(&g_deg[r], w[e]);
}

// --- K3: invd = rsqrt(degree) ---------------------------------------------------
__global__ void k_invd(int n) {
    int i = blockIdx.x * blockDim.x + threadIdx.x;
    if (i < n) g_invd[i] = rsqrtf(g_deg[i]);
}

// --- K4: per-edge p-norm + weighted sum (block reduce -> 1 double atomic) ------
__global__ void __launch_bounds__(256)
k_main(const void* __restrict__ ei,
       const float* __restrict__ w,
       const float4* __restrict__ y4, int E, int N) {
    int e = blockIdx.x * blockDim.x + threadIdx.x;
    const bool is32 = (g_flag != 0u);
    float val = 0.0f;
    if (e < E) {
        int r = load_idx(ei, e, is32);
        int c = load_idx(ei, (long long)E + e, is32);
        if ((unsigned)r < (unsigned)N && (unsigned)c < (unsigned)N) {
            float we = w[e];
            float ir = g_invd[r];
            float ic = g_invd[c];

            const float4* yr = y4 + (size_t)r * 4;
            const float4* yc = y4 + (size_t)c * 4;

            float acc = 0.0f;
            #pragma unroll
            for (int j = 0; j < 4; j++) {
                float4 a = __ldg(yr + j);
                float4 b = __ldg(yc + j);
                float d0 = a.x * ir - b.x * ic;
                float d1 = a.y * ir - b.y * ic;
                float d2 = a.z * ir - b.z * ic;
                float d3 = a.w * ir - b.w * ic;
                acc = fmaf(d0, d0, acc);
                acc = fmaf(d1, d1, acc);
                acc = fmaf(d2, d2, acc);
                acc = fmaf(d3, d3, acc);
            }
            val = sqrtf(acc) * we;
        }
    }

    // warp reduce
    #pragma unroll
    for (int o = 16; o > 0; o >>= 1)
        val += __shfl_down_sync(0xFFFFFFFFu, val, o);

    __shared__ float s_warp[8];
    int lane = threadIdx.x & 31;
    int warp = threadIdx.x >> 5;
    if (lane == 0) s_warp[warp] = val;
    __syncthreads();

    if (warp == 0) {
        val = (lane < (int)(blockDim.x >> 5)) ? s_warp[lane] : 0.0f;
        #pragma unroll
        for (int o = 4; o > 0; o >>= 1)
            val += __shfl_down_sync(0xFFFFFFFFu, val, o);
        if (lane == 0)
            atomicAdd(&g_sum, (double)val);
    }
}

// --- K5: finalize (mean) ---------------------------------------------------------
__global__ void k_final(float* __restrict__ out, int E) {
    *out = (float)(g_sum / (double)E);
}

extern "C" void kernel_launch(void* const* d_in, const int* in_sizes, int n_in,
                              void* d_out, int out_size) {
    const void*   ei  = d_in[0];
    const float*  w   = (const float*)d_in[1];
    const float4* y4  = (const float4*)d_in[2];
    float*        out = (float*)d_out;

    const int E = in_sizes[1];       // number of edges
    const int N = in_sizes[2] / 16;  // number of nodes

    const int T = 256;
    int blocksN = (N + T - 1) / T;
    int blocksE = (E + T - 1) / T;

    k_zero  <<<blocksN, T>>>(N);
    k_detect<<<1, T>>>((const unsigned*)ei, E);
    k_degree<<<blocksE, T>>>(ei, w, E, N);
    k_invd  <<<blocksN, T>>>(N);
    k_main  <<<blocksE, T>>>(ei, w, y4, E, N);
    k_final <<<1, 1>>>(out, E);
}

// round 7
// speedup vs baseline: 1.2398x; 1.2398x over previous
#include <cuda_runtime.h>

// ---------------------------------------------------------------------------
// LaplacianRegularization
//   degree = segment_sum(w, row);  invd = rsqrt(degree)
//   out = mean_e( ||y[row]*invd[row] - y[col]*invd[col]||_2 * w_e )
//
// Inputs (metadata order):
//   d_in[0] : edge_index  int64 OR int32 (2, E)   (dtype detected on-device)
//   d_in[1] : edge_weights float32 (E,)
//   d_in[2] : y            float32 (N, 16)
// Output: 1 float
//
// 3 launches: k_zero (zero scratch + dtype probe), k_degree, k_main
// (fused rsqrt + edge norm + reduce + last-block finalize).
// ---------------------------------------------------------------------------

#define MAX_NODES 131072

__device__ float    g_deg[MAX_NODES];
__device__ double   g_sum;
__device__ unsigned g_flag;    // !=0 => edge_index is int32
__device__ unsigned g_count;   // finished-block ticket

__device__ __forceinline__ int load_idx(const void* ei, long long pos, bool is32) {
    if (is32) return ((const int*)ei)[pos];
    return (int)((const long long*)ei)[pos];
}

// --- K1: zero scratch; block 0 additionally probes the index dtype ----------
// int64 indices < 2^31 have zero hi-words; int32 odd words are node ids
// (nonzero w.h.p. over 4096 samples of U[0,100000)).
__global__ void k_zero(const unsigned* __restrict__ words, int E, int n) {
    int i = blockIdx.x * blockDim.x + threadIdx.x;
    if (i < n) g_deg[i] = 0.0f;
    if (i == 0) { g_sum = 0.0; g_count = 0u; }

    if (blockIdx.x == 0) {
        int samples = E < 4096 ? E : 4096;
        unsigned v = 0;
        for (int s = threadIdx.x; s < samples; s += blockDim.x)
            v |= words[2 * s + 1];
        #pragma unroll
        for (int o = 16; o > 0; o >>= 1)
            v |= __shfl_xor_sync(0xFFFFFFFFu, v, o);
        __shared__ unsigned sh[8];
        int lane = threadIdx.x & 31, warp = threadIdx.x >> 5;
        if (lane == 0) sh[warp] = v;
        __syncthreads();
        if (threadIdx.x == 0) {
            unsigned r = 0;
            for (int k = 0; k < (int)(blockDim.x >> 5); k++) r |= sh[k];
            g_flag = r;
        }
    }
}

// --- K2: degree = segment_sum(w, row) ----------------------------------------
__global__ void k_degree(const void* __restrict__ ei,
                         const float* __restrict__ w, int E, int N) {
    int e = blockIdx.x * blockDim.x + threadIdx.x;
    if (e >= E) return;
    const bool is32 = (g_flag != 0u);
    int r = load_idx(ei, e, is32);
    if ((unsigned)r < (unsigned)N)
        atomicAdd(&g_deg[r], w[e]);
}

// --- K3: fused rsqrt + per-edge norm + reduce + finalize ----------------------
// Layout: 4 threads (a quad) per edge; each quad handles 4 consecutive edges
// per iteration. 256 threads/block -> 64 quads -> 256 edges per block.
#define EDGES_PER_BLOCK 256

__global__ void __launch_bounds__(256)
k_main(const void* __restrict__ ei,
       const float* __restrict__ w,
       const float4* __restrict__ y4,
       float* __restrict__ out, int E, int N, int nblocks) {
    const bool is32  = (g_flag != 0u);
    const int  lane4 = threadIdx.x & 3;
    const int  qid   = threadIdx.x >> 2;
    const long long base = (long long)blockIdx.x * EDGES_PER_BLOCK + (long long)qid * 4;

    int   r[4], c[4];
    float we[4];
    bool  full = (base + 3 < (long long)E);

    if (full) {
        if (is32) {
            const int4 rv = __ldg((const int4*)((const int*)ei + base));
            const int4 cv = __ldg((const int4*)((const int*)ei + (long long)E + base));
            r[0] = rv.x; r[1] = rv.y; r[2] = rv.z; r[3] = rv.w;
            c[0] = cv.x; c[1] = cv.y; c[2] = cv.z; c[3] = cv.w;
        } else {
            const longlong2 r01 = __ldg((const longlong2*)((const long long*)ei + base));
            const longlong2 r23 = __ldg((const longlong2*)((const long long*)ei + base + 2));
            const longlong2 c01 = __ldg((const longlong2*)((const long long*)ei + (long long)E + base));
            const longlong2 c23 = __ldg((const longlong2*)((const long long*)ei + (long long)E + base + 2));
            r[0] = (int)r01.x; r[1] = (int)r01.y; r[2] = (int)r23.x; r[3] = (int)r23.y;
            c[0] = (int)c01.x; c[1] = (int)c01.y; c[2] = (int)c23.x; c[3] = (int)c23.y;
        }
        const float4 wv = __ldg((const float4*)(w + base));
        we[0] = wv.x; we[1] = wv.y; we[2] = wv.z; we[3] = wv.w;
    } else {
        #pragma unroll
        for (int k = 0; k < 4; k++) {
            long long e = base + k;
            if (e < (long long)E) {
                r[k]  = load_idx(ei, e, is32);
                c[k]  = load_idx(ei, (long long)E + e, is32);
                we[k] = w[e];
            } else { r[k] = -1; c[k] = -1; we[k] = 0.0f; }
        }
    }

    // Issue all 8 y-row loads (4 edges x {row,col} x one float4 per lane).
    float4 a[4], b[4];
    float  ir[4], ic[4];
    #pragma unroll
    for (int k = 0; k < 4; k++) {
        bool ok = ((unsigned)r[k] < (unsigned)N) && ((unsigned)c[k] < (unsigned)N);
        if (ok) {
            a[k]  = __ldg(y4 + (size_t)r[k] * 4 + lane4);
            b[k]  = __ldg(y4 + (size_t)c[k] * 4 + lane4);
            ir[k] = rsqrtf(g_deg[r[k]]);
            ic[k] = rsqrtf(g_deg[c[k]]);
        } else {
            a[k] = make_float4(0,0,0,0); b[k] = make_float4(0,0,0,0);
            ir[k] = 0.0f; ic[k] = 0.0f; we[k] = 0.0f;
        }
    }

    float val = 0.0f;
    #pragma unroll
    for (int k = 0; k < 4; k++) {
        float d0 = a[k].x * ir[k] - b[k].x * ic[k];
        float d1 = a[k].y * ir[k] - b[k].y * ic[k];
        float d2 = a[k].z * ir[k] - b[k].z * ic[k];
        float d3 = a[k].w * ir[k] - b[k].w * ic[k];
        float acc = d0 * d0;
        acc = fmaf(d1, d1, acc);
        acc = fmaf(d2, d2, acc);
        acc = fmaf(d3, d3, acc);
        // quad reduce (lanes differ only in lane4 bits)
        acc += __shfl_xor_sync(0xFFFFFFFFu, acc, 1);
        acc += __shfl_xor_sync(0xFFFFFFFFu, acc, 2);
        if (lane4 == 0) val += sqrtf(acc) * we[k];
    }

    // warp + block reduce
    #pragma unroll
    for (int o = 16; o > 0; o >>= 1)
        val += __shfl_down_sync(0xFFFFFFFFu, val, o);

    __shared__ float s_warp[8];
    int lane = threadIdx.x & 31;
    int warp = threadIdx.x >> 5;
    if (lane == 0) s_warp[warp] = val;
    __syncthreads();

    if (warp == 0) {
        val = (lane < (int)(blockDim.x >> 5)) ? s_warp[lane] : 0.0f;
        #pragma unroll
        for (int o = 4; o > 0; o >>= 1)
            val += __shfl_down_sync(0xFFFFFFFFu, val, o);
        if (lane == 0) {
            atomicAdd(&g_sum, (double)val);
            __threadfence();
            unsigned ticket = atomicInc(&g_count, 0xFFFFFFFFu);
            if (ticket == (unsigned)(nblocks - 1))
                *out = (float)(g_sum / (double)E);
        }
    }
}

extern "C" void kernel_launch(void* const* d_in, const int* in_sizes, int n_in,
                              void* d_out, int out_size) {
    const void*   ei  = d_in[0];
    const float*  w   = (const float*)d_in[1];
    const float4* y4  = (const float4*)d_in[2];
    float*        out = (float*)d_out;

    const int E = in_sizes[1];       // number of edges
    const int N = in_sizes[2] / 16;  // number of nodes

    const int T = 256;
    int blocksN = (N + T - 1) / T;
    int blocksE = (E + T - 1) / T;
    int blocksM = (E + EDGES_PER_BLOCK - 1) / EDGES_PER_BLOCK;

    k_zero  <<<blocksN, T>>>((const unsigned*)ei, E, N);
    k_degree<<<blocksE, T>>>(ei, w, E, N);
    k_main  <<<blocksM, T>>>(ei, w, y4, out, E, N, blocksM);
}

// round 8
// speedup vs baseline: 1.5341x; 1.2374x over previous
#include <cuda_runtime.h>

// ---------------------------------------------------------------------------
// LaplacianRegularization
//   degree = segment_sum(w, row);  ys = y * rsqrt(degree)[:,None]
//   out = mean_e( ||ys[row] - ys[col]||_2 * w_e )
//
// Inputs (metadata order):
//   d_in[0] : edge_index  int64 OR int32 (2, E)   (dtype detected on-device)
//   d_in[1] : edge_weights float32 (E,)
//   d_in[2] : y            float32 (N, 16)
// Output: 1 float
//
// 4 launches:
//   k_zero   : zero degree scratch + dtype probe
//   k_degree : segment-sum atomics
//   k_scale  : ys = y * rsqrt(degree)   (kills all per-edge degree gathers)
//   k_main   : per-edge norm + reduce + last-block finalize
// ---------------------------------------------------------------------------

#define MAX_NODES 131072

__device__ float    g_deg[MAX_NODES];
__device__ float4   g_ys[MAX_NODES * 4];   // scaled y rows, 4 x float4 per node
__device__ double   g_sum;
__device__ unsigned g_flag;    // !=0 => edge_index is int32
__device__ unsigned g_count;   // finished-block ticket

__device__ __forceinline__ int load_idx(const void* ei, long long pos, bool is32) {
    if (is32) return ((const int*)ei)[pos];
    return (int)((const long long*)ei)[pos];
}

// --- K1: zero scratch; block 0 probes the index dtype -----------------------
// int64 indices < 2^31 have zero hi-words; int32 odd words are node ids
// (nonzero w.h.p. over 1024 samples of U[0,100000)).
__global__ void k_zero(const unsigned* __restrict__ words, int E, int n) {
    int i = blockIdx.x * blockDim.x + threadIdx.x;
    // 128-bit zero stores over g_deg
    int n4 = (n + 3) >> 2;
    if (i < n4) ((float4*)g_deg)[i] = make_float4(0, 0, 0, 0);
    if (i == 0) { g_sum = 0.0; g_count = 0u; }

    if (blockIdx.x == 0) {
        int samples = E < 1024 ? E : 1024;
        unsigned v = 0;
        for (int s = threadIdx.x; s < samples; s += blockDim.x)
            v |= words[2 * s + 1];
        #pragma unroll
        for (int o = 16; o > 0; o >>= 1)
            v |= __shfl_xor_sync(0xFFFFFFFFu, v, o);
        __shared__ unsigned sh[8];
        int lane = threadIdx.x & 31, warp = threadIdx.x >> 5;
        if (lane == 0) sh[warp] = v;
        __syncthreads();
        if (threadIdx.x == 0) {
            unsigned r = 0;
            for (int k = 0; k < (int)(blockDim.x >> 5); k++) r |= sh[k];
            g_flag = r;
        }
    }
}

// --- K2: degree = segment_sum(w, row) ----------------------------------------
__global__ void k_degree(const void* __restrict__ ei,
                         const float* __restrict__ w, int E, int N) {
    int e = blockIdx.x * blockDim.x + threadIdx.x;
    if (e >= E) return;
    const bool is32 = (g_flag != 0u);
    int r = load_idx(ei, e, is32);
    if ((unsigned)r < (unsigned)N)
        atomicAdd(&g_deg[r], w[e]);
}

// --- K3: ys = y * rsqrt(degree) ------------------------------------------------
// One thread per float4 (4 threads per node row).
__global__ void k_scale(const float4* __restrict__ y4, int N) {
    int i = blockIdx.x * blockDim.x + threadIdx.x;   // float4 index
    if (i >= N * 4) return;
    int node = i >> 2;
    float s = rsqrtf(g_deg[node]);
    float4 v = __ldg(y4 + i);
    v.x *= s; v.y *= s; v.z *= s; v.w *= s;
    g_ys[i] = v;
}

// --- K4: per-edge norm + reduce + finalize -------------------------------------
// Quad layout: 4 lanes per edge (one float4 each); 4 edges per quad.
#define EDGES_PER_BLOCK 256

__global__ void __launch_bounds__(256)
k_main(const void* __restrict__ ei,
       const float* __restrict__ w,
       float* __restrict__ out, int E, int N, int nblocks) {
    const bool is32  = (g_flag != 0u);
    const int  lane4 = threadIdx.x & 3;
    const int  qid   = threadIdx.x >> 2;
    const long long base = (long long)blockIdx.x * EDGES_PER_BLOCK + (long long)qid * 4;

    int   r[4], c[4];
    float we[4];
    bool  full = (base + 3 < (long long)E);

    if (full) {
        if (is32) {
            const int4 rv = __ldg((const int4*)((const int*)ei + base));
            const int4 cv = __ldg((const int4*)((const int*)ei + (long long)E + base));
            r[0] = rv.x; r[1] = rv.y; r[2] = rv.z; r[3] = rv.w;
            c[0] = cv.x; c[1] = cv.y; c[2] = cv.z; c[3] = cv.w;
        } else {
            const longlong2 r01 = __ldg((const longlong2*)((const long long*)ei + base));
            const longlong2 r23 = __ldg((const longlong2*)((const long long*)ei + base + 2));
            const longlong2 c01 = __ldg((const longlong2*)((const long long*)ei + (long long)E + base));
            const longlong2 c23 = __ldg((const longlong2*)((const long long*)ei + (long long)E + base + 2));
            r[0] = (int)r01.x; r[1] = (int)r01.y; r[2] = (int)r23.x; r[3] = (int)r23.y;
            c[0] = (int)c01.x; c[1] = (int)c01.y; c[2] = (int)c23.x; c[3] = (int)c23.y;
        }
        const float4 wv = __ldg((const float4*)(w + base));
        we[0] = wv.x; we[1] = wv.y; we[2] = wv.z; we[3] = wv.w;
    } else {
        #pragma unroll
        for (int k = 0; k < 4; k++) {
            long long e = base + k;
            if (e < (long long)E) {
                r[k]  = load_idx(ei, e, is32);
                c[k]  = load_idx(ei, (long long)E + e, is32);
                we[k] = w[e];
            } else { r[k] = -1; c[k] = -1; we[k] = 0.0f; }
        }
    }

    // 8 independent random row-gathers per thread (max MLP, no deg gathers).
    float4 a[4], b[4];
    #pragma unroll
    for (int k = 0; k < 4; k++) {
        bool ok = ((unsigned)r[k] < (unsigned)N) && ((unsigned)c[k] < (unsigned)N);
        if (ok) {
            a[k] = g_ys[(size_t)r[k] * 4 + lane4];
            b[k] = g_ys[(size_t)c[k] * 4 + lane4];
        } else {
            a[k] = make_float4(0, 0, 0, 0);
            b[k] = make_float4(0, 0, 0, 0);
            we[k] = 0.0f;
        }
    }

    float val = 0.0f;
    #pragma unroll
    for (int k = 0; k < 4; k++) {
        float d0 = a[k].x - b[k].x;
        float d1 = a[k].y - b[k].y;
        float d2 = a[k].z - b[k].z;
        float d3 = a[k].w - b[k].w;
        float acc = d0 * d0;
        acc = fmaf(d1, d1, acc);
        acc = fmaf(d2, d2, acc);
        acc = fmaf(d3, d3, acc);
        // quad reduce (lanes differ only in lane4 bits)
        acc += __shfl_xor_sync(0xFFFFFFFFu, acc, 1);
        acc += __shfl_xor_sync(0xFFFFFFFFu, acc, 2);
        if (lane4 == 0) val += sqrtf(acc) * we[k];
    }

    // warp + block reduce
    #pragma unroll
    for (int o = 16; o > 0; o >>= 1)
        val += __shfl_down_sync(0xFFFFFFFFu, val, o);

    __shared__ float s_warp[8];
    int lane = threadIdx.x & 31;
    int warp = threadIdx.x >> 5;
    if (lane == 0) s_warp[warp] = val;
    __syncthreads();

    if (warp == 0) {
        val = (lane < (int)(blockDim.x >> 5)) ? s_warp[lane] : 0.0f;
        #pragma unroll
        for (int o = 4; o > 0; o >>= 1)
            val += __shfl_down_sync(0xFFFFFFFFu, val, o);
        if (lane == 0) {
            atomicAdd(&g_sum, (double)val);
            __threadfence();
            unsigned ticket = atomicInc(&g_count, 0xFFFFFFFFu);
            if (ticket == (unsigned)(nblocks - 1))
                *out = (float)(g_sum / (double)E);
        }
    }
}

extern "C" void kernel_launch(void* const* d_in, const int* in_sizes, int n_in,
                              void* d_out, int out_size) {
    const void*   ei  = d_in[0];
    const float*  w   = (const float*)d_in[1];
    const float4* y4  = (const float4*)d_in[2];
    float*        out = (float*)d_out;

    const int E = in_sizes[1];       // number of edges
    const int N = in_sizes[2] / 16;  // number of nodes

    const int T = 256;
    int blocksZ = ((N + 3) / 4 + T - 1) / T;
    int blocksE = (E + T - 1) / T;
    int blocksS = (N * 4 + T - 1) / T;
    int blocksM = (E + EDGES_PER_BLOCK - 1) / EDGES_PER_BLOCK;

    k_zero  <<<blocksZ, T>>>((const unsigned*)ei, E, N);
    k_degree<<<blocksE, T>>>(ei, w, E, N);
    k_scale <<<blocksS, T>>>(y4, N);
    k_main  <<<blocksM, T>>>(ei, w, out, E, N, blocksM);
}